// round 10
// baseline (speedup 1.0000x reference)
#include <cuda_runtime.h>
#include <cstdint>
#include <cstddef>

#define T_STEPS 1024
#define BATCH   64
#define FDIM    256
#define HDIM    512
#define G3      (3*HDIM)   /* 1536 */

typedef unsigned long long ull;

// ---------------- static scratch (allocation-free per harness rules) ----------------
__device__ float    g_xg[(size_t)T_STEPS * BATCH * G3];   // input projections
__device__ float    g_h[2][BATCH * HDIM];                 // ping-pong hidden state [b][pos8(k)]
__device__ unsigned g_bar[8 * 32];                        // per-batch-group barrier (padded lines)

// ---------------- helpers ----------------
__device__ __forceinline__ ull ffma2(ull a, ull b, ull c) {
    ull d;
    asm("fma.rn.f32x2 %0, %1, %2, %3;" : "=l"(d) : "l"(a), "l"(b), "l"(c));
    return d;
}
__device__ __forceinline__ ull dup2(float a) {
    ull d;
    asm("mov.b64 %0, {%1, %1};" : "=l"(d) : "f"(a));
    return d;
}
__device__ __forceinline__ float lo32(ull v) { return __int_as_float((int)(unsigned)(v & 0xffffffffull)); }
__device__ __forceinline__ float hi32(ull v) { return __int_as_float((int)(unsigned)(v >> 32)); }
__device__ __forceinline__ float sigm(float x) { return 1.0f / (1.0f + __expf(-x)); }

// release-add / acquire-load for the inter-CTA barrier (no full membars needed)
__device__ __forceinline__ void bar_signal(unsigned* p) {
    asm volatile("red.release.gpu.global.add.u32 [%0], 1;" :: "l"(p) : "memory");
}
__device__ __forceinline__ unsigned bar_peek(const unsigned* p) {
    unsigned v;
    asm volatile("ld.acquire.gpu.global.u32 %0, [%1];" : "=r"(v) : "l"(p) : "memory");
    return v;
}

// 8-slice k-permutation: k = ks*64 + cc*4 + j  ->  pos = cc*32 + ks*4 + j
// (each of the 8 k-slices becomes chunk-contiguous, 16B-aligned)
__device__ __forceinline__ int kpos8(int k) {
    return (((k >> 2) & 15) << 5) + ((k >> 6) << 2) + (k & 3);
}

// ---------------- kernel 0: init (barrier reset + h0 permuted copy) ----------------
__global__ void init_kernel(const float* __restrict__ h0) {
    if (blockIdx.x == 0 && threadIdx.x < 8 * 32) g_bar[threadIdx.x] = 0u;
    int idx = blockIdx.x * blockDim.x + threadIdx.x;
    if (idx < BATCH * HDIM) {
        int b = idx >> 9;
        int k = idx & 511;
        g_h[0][b * HDIM + kpos8(k)] = h0[idx];
    }
}

// ---------------- kernel 1: xg = x @ Wi + bi  (128x128x16 tile, 8x8/thread) ----------------
#define GBM 128
#define GBN 128
#define GBK 16
#define APITCH 132

__global__ __launch_bounds__(256) void xg_gemm(const float* __restrict__ X,
                                               const float* __restrict__ Wi,
                                               const float* __restrict__ bi) {
    __shared__ float At[GBK * APITCH];   // transposed A: At[k][m]
    __shared__ float Bs[GBK * GBN];      // Bs[k][n]

    const int tid = threadIdx.x;
    const int tx  = tid & 15;            // n-group
    const int ty  = tid >> 4;            // m-group
    const size_t m0 = (size_t)blockIdx.y * GBM;
    const int    n0 = blockIdx.x * GBN;

    const int arow = tid >> 2;           // 0..63
    const int ac4  = (tid & 3) << 2;     // 0,4,8,12
    const int brow = tid >> 5;           // 0..7
    const int bc4  = (tid & 31) << 2;    // 0..124

    const float* Xp = X + m0 * FDIM;
    const float* Wp = Wi + n0;

    ull acc[8][4];
    #pragma unroll
    for (int m = 0; m < 8; m++)
        #pragma unroll
        for (int n = 0; n < 4; n++) acc[m][n] = 0ull;

    float4 a0r = *(const float4*)(Xp + (size_t)arow        * FDIM + ac4);
    float4 a1r = *(const float4*)(Xp + (size_t)(arow + 64) * FDIM + ac4);
    float4 b0r = *(const float4*)(Wp + (size_t)brow       * G3 + bc4);
    float4 b1r = *(const float4*)(Wp + (size_t)(brow + 8) * G3 + bc4);

    for (int k0 = 0; k0 < FDIM; k0 += GBK) {
        At[(ac4 + 0) * APITCH + arow] = a0r.x;
        At[(ac4 + 1) * APITCH + arow] = a0r.y;
        At[(ac4 + 2) * APITCH + arow] = a0r.z;
        At[(ac4 + 3) * APITCH + arow] = a0r.w;
        At[(ac4 + 0) * APITCH + arow + 64] = a1r.x;
        At[(ac4 + 1) * APITCH + arow + 64] = a1r.y;
        At[(ac4 + 2) * APITCH + arow + 64] = a1r.z;
        At[(ac4 + 3) * APITCH + arow + 64] = a1r.w;
        *(float4*)&Bs[brow * GBN + bc4]       = b0r;
        *(float4*)&Bs[(brow + 8) * GBN + bc4] = b1r;
        __syncthreads();

        if (k0 + GBK < FDIM) {
            a0r = *(const float4*)(Xp + (size_t)arow        * FDIM + k0 + GBK + ac4);
            a1r = *(const float4*)(Xp + (size_t)(arow + 64) * FDIM + k0 + GBK + ac4);
            b0r = *(const float4*)(Wp + (size_t)(k0 + GBK + brow)     * G3 + bc4);
            b1r = *(const float4*)(Wp + (size_t)(k0 + GBK + brow + 8) * G3 + bc4);
        }

        #pragma unroll
        for (int k = 0; k < GBK; k++) {
            float4 av0 = *(const float4*)&At[k * APITCH + ty * 8];
            float4 av1 = *(const float4*)&At[k * APITCH + ty * 8 + 4];
            ulonglong2 bv0 = *(const ulonglong2*)&Bs[k * GBN + tx * 8];
            ulonglong2 bv1 = *(const ulonglong2*)&Bs[k * GBN + tx * 8 + 4];
            float am[8] = {av0.x, av0.y, av0.z, av0.w, av1.x, av1.y, av1.z, av1.w};
            #pragma unroll
            for (int m = 0; m < 8; m++) {
                ull d = dup2(am[m]);
                acc[m][0] = ffma2(d, bv0.x, acc[m][0]);
                acc[m][1] = ffma2(d, bv0.y, acc[m][1]);
                acc[m][2] = ffma2(d, bv1.x, acc[m][2]);
                acc[m][3] = ffma2(d, bv1.y, acc[m][3]);
            }
        }
        __syncthreads();
    }

    float4 bias0 = *(const float4*)(bi + n0 + tx * 8);
    float4 bias1 = *(const float4*)(bi + n0 + tx * 8 + 4);
    #pragma unroll
    for (int m = 0; m < 8; m++) {
        size_t row = m0 + (size_t)ty * 8 + m;
        float4 o0, o1;
        o0.x = lo32(acc[m][0]) + bias0.x;  o0.y = hi32(acc[m][0]) + bias0.y;
        o0.z = lo32(acc[m][1]) + bias0.z;  o0.w = hi32(acc[m][1]) + bias0.w;
        o1.x = lo32(acc[m][2]) + bias1.x;  o1.y = hi32(acc[m][2]) + bias1.y;
        o1.z = lo32(acc[m][3]) + bias1.z;  o1.w = hi32(acc[m][3]) + bias1.w;
        *(float4*)(g_xg + row * G3 + n0 + tx * 8)     = o0;
        *(float4*)(g_xg + row * G3 + n0 + tx * 8 + 4) = o1;
    }
}

// ---------------- kernel 2: persistent GRU scan ----------------
// 128 blocks = 8 batch-groups x 16 col-groups; barrier across the 16 CTAs of a
// batch-group only. 256 threads: warp = col-quad (cols warp*4..+3), lane =
// bq*8 + ks  (bq -> batches 2bq,2bq+1; ks = 8-way k-split). w-LDS 4x lane-
// deduped; acc = 2 batches x 12 gate-cols = 24 ull regs; 1-round shuffle reduce.
#define RBLOCKS   128
#define RTHREADS  256
#define WSZ       (96 * 512)
#define HSZ       (8 * 512)
#define RSTRIDE   97                      /* 24 sums x 4 partials + pad */
#define RSZ       (32 * RSTRIDE)
#define SMEM_REC  ((WSZ + HSZ + RSZ) * 4) /* 225408 B */

__global__ __launch_bounds__(RTHREADS, 1) void gru_rec(const float* __restrict__ Wh,
                                                       const float* __restrict__ bhn,
                                                       float* __restrict__ ys) {
    extern __shared__ float smem[];
    float* w_s   = smem;               // 96 rows (c*3+g) x 512 (pos8 k)
    float* h_s   = smem + WSZ;         // 8 rows (batch)  x 512 (pos8 k)
    float* red_s = h_s + HSZ;          // 32 positions x RSTRIDE

    const int tid  = threadIdx.x;
    const int lane = tid & 31;
    const int warp = tid >> 5;           // col-quad 0..7
    const int bq   = lane >> 3;          // batch-pair 0..3 (batches 2bq, 2bq+1)
    const int ks   = lane & 7;           // k-slice 0..7

    const int bg = blockIdx.x >> 4;      // batch group 0..7
    const int cg = blockIdx.x & 15;      // col group 0..15
    unsigned* barp = &g_bar[bg * 32];

    // epilogue identity: thread -> one (batch, H-col) output
    const int lb    = tid >> 5;          // 0..7
    const int lc    = tid & 31;          // 0..31
    const int bglob = bg * 8 + lb;
    const int colg  = cg * 32 + lc;
    const int posc  = ((((cg & 1) << 3) + (lc >> 2)) << 5) + ((cg >> 1) << 2) + (lc & 3); // kpos8(colg)
    const float bh  = bhn[colg];

    // ---- stage Wh slice once (pos8-permuted k) ----
    for (int idx = tid; idx < 96 * 512; idx += RTHREADS) {
        int k = idx / 96;
        int m = idx - k * 96;
        int g = m >> 5, c = m & 31;
        float v = Wh[(size_t)k * G3 + g * HDIM + cg * 32 + c];
        w_s[(c * 3 + g) * 512 + kpos8(k)] = v;
    }
    __syncthreads();

    const float* hb = h_s + (bq * 2) * 512 + ks * 4;
    const float* wb = w_s + warp * 12 * 512 + ks * 4;
    const float* xgq = g_xg + (size_t)bglob * G3 + colg;

    // prefetch xg for t=0
    float xr = __ldg(xgq);
    float xz = __ldg(xgq + HDIM);
    float xn = __ldg(xgq + 2 * HDIM);

    for (int t = 0; t < T_STEPS; t++) {
        // ---- stage h slice (16KB straight copy; src already pos8-permuted) ----
        const float4* hsrc = (const float4*)(g_h[t & 1] + (size_t)bg * 8 * HDIM);
        float4 v0 = __ldcg(hsrc + tid);
        float4 v1 = __ldcg(hsrc + 256 + tid);
        float4 v2 = __ldcg(hsrc + 512 + tid);
        float4 v3 = __ldcg(hsrc + 768 + tid);
        ((float4*)h_s)[tid]       = v0;
        ((float4*)h_s)[256 + tid] = v1;
        ((float4*)h_s)[512 + tid] = v2;
        ((float4*)h_s)[768 + tid] = v3;
        __syncthreads();

        // ---- register-tiled dots: 2 batches x 12 gate-cols x 64 k ----
        ull acc[2][12];
        #pragma unroll
        for (int b = 0; b < 2; b++)
            #pragma unroll
            for (int i = 0; i < 12; i++) acc[b][i] = 0ull;

        #pragma unroll 4
        for (int cc = 0; cc < 16; cc++) {
            const float* hc = hb + cc * 32;
            const float* wc = wb + cc * 32;
            ulonglong2 hv0 = *(const ulonglong2*)hc;
            ulonglong2 hv1 = *(const ulonglong2*)(hc + 512);
            #pragma unroll
            for (int i = 0; i < 12; i++) {
                ulonglong2 wv = *(const ulonglong2*)(wc + i * 512);
                acc[0][i] = ffma2(hv0.x, wv.x, acc[0][i]);
                acc[0][i] = ffma2(hv0.y, wv.y, acc[0][i]);
                acc[1][i] = ffma2(hv1.x, wv.x, acc[1][i]);
                acc[1][i] = ffma2(hv1.y, wv.y, acc[1][i]);
            }
        }

        // ---- fold f32x2 -> f32, 1 shuffle round (8 ks -> 4 partials) ----
        float s[24];
        #pragma unroll
        for (int b = 0; b < 2; b++)
            #pragma unroll
            for (int i = 0; i < 12; i++) {
                ull v = acc[b][i];
                s[b * 12 + i] = lo32(v) + hi32(v);
            }
        #pragma unroll
        for (int i = 0; i < 24; i++) s[i] += __shfl_xor_sync(0xffffffffu, s[i], 4);

        if ((lane & 4) == 0) {
            // position index = bq*8 + warp ; partial p = ks&3
            float* rp = red_s + (bq * 8 + warp) * RSTRIDE + (ks & 3);
            #pragma unroll
            for (int i = 0; i < 24; i++) rp[i * 4] = s[i];
        }
        __syncthreads();

        // ---- gather 4 partials x 3 gates, compute GRU update ----
        // position = (lb>>1)*8 + (lc>>2); sum index = (lb&1)*12 + (lc&3)*3 + gate
        const float* rp = red_s + ((lb >> 1) * 8 + (lc >> 2)) * RSTRIDE
                        + ((lb & 1) * 12 + (lc & 3) * 3) * 4;
        float hr = rp[0] + rp[1] + rp[2]  + rp[3];
        float hz = rp[4] + rp[5] + rp[6]  + rp[7];
        float hn = rp[8] + rp[9] + rp[10] + rp[11];
        float hold = h_s[lb * 512 + posc];
        float r = sigm(xr + hr);
        float z = sigm(xz + hz);
        float n = tanhf(xn + r * (hn + bh));
        float hnew = (1.0f - z) * n + z * hold;

        // h store must precede the release; ys store + xg prefetch hide in the spin
        __stcg(&g_h[(t + 1) & 1][bglob * HDIM + posc], hnew);
        __syncthreads();
        if (tid == 0) bar_signal(barp);

        ys[((size_t)t * BATCH + bglob) * HDIM + colg] = hnew;
        float nxr = 0.f, nxz = 0.f, nxn = 0.f;
        if (t + 1 < T_STEPS) {
            const float* xb = xgq + (size_t)(t + 1) * (BATCH * G3);
            nxr = __ldg(xb);
            nxz = __ldg(xb + HDIM);
            nxn = __ldg(xb + 2 * HDIM);
        }

        if (tid == 0) {
            unsigned target = 16u * (unsigned)(t + 1);
            while (bar_peek(barp) < target) { }
        }
        __syncthreads();
        xr = nxr; xz = nxz; xn = nxn;
    }
}

// ---------------- launcher ----------------
extern "C" void kernel_launch(void* const* d_in, const int* in_sizes, int n_in,
                              void* d_out, int out_size) {
    (void)in_sizes; (void)n_in; (void)out_size;
    const float* x   = (const float*)d_in[0];
    const float* h0  = (const float*)d_in[1];
    const float* Wi  = (const float*)d_in[2];
    const float* bi  = (const float*)d_in[3];
    const float* Wh  = (const float*)d_in[4];
    const float* bhn = (const float*)d_in[5];
    float* ys = (float*)d_out;

    cudaFuncSetAttribute(gru_rec, cudaFuncAttributeMaxDynamicSharedMemorySize, SMEM_REC);

    init_kernel<<<64, 512>>>(h0);

    dim3 ggrid(G3 / GBN, (T_STEPS * BATCH) / GBM);   // 12 x 512
    xg_gemm<<<ggrid, 256>>>(x, Wi, bi);

    gru_rec<<<RBLOCKS, RTHREADS, SMEM_REC>>>(Wh, bhn, ys);
}